// round 2
// baseline (speedup 1.0000x reference)
#include <cuda_runtime.h>

// AbstractRelu (DeepPoly ReLU relaxation), elementwise over N fp32.
// out layout: [relu(x) (N)] [lb_slope*low (N)] [relu(high) (N)]
//
// R2: streaming cache hints (__ldcs/__stcs) + 2 grid-strided float4 quads
// per thread for deeper MLP and fewer blocks.

#define QUADS_PER_THREAD 2

__global__ void __launch_bounds__(256, 8)
abstract_relu_kernel(const float4* __restrict__ x,
                     const float4* __restrict__ low,
                     const float4* __restrict__ high,
                     float4* __restrict__ x_out,
                     float4* __restrict__ low_out,
                     float4* __restrict__ high_out,
                     int n4)
{
    const int stride = blockDim.x * gridDim.x;
    int i = blockIdx.x * blockDim.x + threadIdx.x;

    float4 xv[QUADS_PER_THREAD], lv[QUADS_PER_THREAD], hv[QUADS_PER_THREAD];
    int idx[QUADS_PER_THREAD];

    // Front-batch all loads (deep MLP, evict-first: no reuse of this stream)
    #pragma unroll
    for (int q = 0; q < QUADS_PER_THREAD; q++) {
        idx[q] = i + q * stride;
        if (idx[q] < n4) {
            xv[q] = __ldcs(&x[idx[q]]);
            lv[q] = __ldcs(&low[idx[q]]);
            hv[q] = __ldcs(&high[idx[q]]);
        }
    }

    #pragma unroll
    for (int q = 0; q < QUADS_PER_THREAD; q++) {
        if (idx[q] >= n4) continue;

        float4 xo, lo, ho;

        #define LANE(f)                                                       \
        {                                                                     \
            float xe = xv[q].f, le = lv[q].f, he = hv[q].f;                   \
            xo.f = fmaxf(xe, 0.0f);                                           \
            ho.f = fmaxf(he, 0.0f);                                           \
            bool zero = (he <= 0.0f) || (le < 0.0f && le * le > he * he);     \
            lo.f = zero ? 0.0f : le;                                          \
        }

        LANE(x) LANE(y) LANE(z) LANE(w)
        #undef LANE

        __stcs(&x_out[idx[q]],    xo);
        __stcs(&low_out[idx[q]],  lo);
        __stcs(&high_out[idx[q]], ho);
    }
}

extern "C" void kernel_launch(void* const* d_in, const int* in_sizes, int n_in,
                              void* d_out, int out_size)
{
    const float* x    = (const float*)d_in[0];
    const float* low  = (const float*)d_in[1];
    const float* high = (const float*)d_in[2];
    float* out = (float*)d_out;

    const int n  = in_sizes[0];          // 16777216
    const int n4 = n / 4;                // 4194304, divisible by 4

    float* x_out    = out;
    float* low_out  = out + n;
    float* high_out = out + 2 * (size_t)n;

    const int threads = 256;
    const int work    = threads * QUADS_PER_THREAD;
    const int blocks  = (n4 + work - 1) / work;   // 8192

    abstract_relu_kernel<<<blocks, threads>>>(
        (const float4*)x, (const float4*)low, (const float4*)high,
        (float4*)x_out, (float4*)low_out, (float4*)high_out, n4);
}

// round 3
// speedup vs baseline: 1.0327x; 1.0327x over previous
#include <cuda_runtime.h>

// AbstractRelu (DeepPoly ReLU relaxation), elementwise over N fp32.
// out layout: [relu(x) (N)] [lb_slope*low (N)] [relu(high) (N)]
//
// R3: R1 structure restored (1 float4 quad per thread, MLP_p1=3 —
// the grid-strided 2-quad variant regressed via L1tex queue contention).
// Single isolated change vs R1: streaming cache hints (__ldcs/__stcs),
// since this is a pure one-pass 402MB stream with zero L2 reuse.

__global__ void __launch_bounds__(256, 8)
abstract_relu_kernel(const float4* __restrict__ x,
                     const float4* __restrict__ low,
                     const float4* __restrict__ high,
                     float4* __restrict__ x_out,
                     float4* __restrict__ low_out,
                     float4* __restrict__ high_out,
                     int n4)
{
    int i = blockIdx.x * blockDim.x + threadIdx.x;
    if (i >= n4) return;

    float4 xv = __ldcs(&x[i]);
    float4 lv = __ldcs(&low[i]);
    float4 hv = __ldcs(&high[i]);

    float4 xo, lo, ho;

    #define LANE(f)                                                        \
    {                                                                      \
        float xe = xv.f, le = lv.f, he = hv.f;                             \
        xo.f = fmaxf(xe, 0.0f);                                            \
        ho.f = fmaxf(he, 0.0f);                                            \
        bool zero = (he <= 0.0f) || (le < 0.0f && le * le > he * he);      \
        lo.f = zero ? 0.0f : le;                                           \
    }

    LANE(x) LANE(y) LANE(z) LANE(w)
    #undef LANE

    __stcs(&x_out[i],    xo);
    __stcs(&low_out[i],  lo);
    __stcs(&high_out[i], ho);
}

extern "C" void kernel_launch(void* const* d_in, const int* in_sizes, int n_in,
                              void* d_out, int out_size)
{
    const float* x    = (const float*)d_in[0];
    const float* low  = (const float*)d_in[1];
    const float* high = (const float*)d_in[2];
    float* out = (float*)d_out;

    const int n  = in_sizes[0];          // 16777216
    const int n4 = n / 4;                // 4194304

    float* x_out    = out;
    float* low_out  = out + n;
    float* high_out = out + 2 * (size_t)n;

    const int threads = 256;
    const int blocks  = (n4 + threads - 1) / threads;  // 16384

    abstract_relu_kernel<<<blocks, threads>>>(
        (const float4*)x, (const float4*)low, (const float4*)high,
        (float4*)x_out, (float4*)low_out, (float4*)high_out, n4);
}